// round 1
// baseline (speedup 1.0000x reference)
#include <cuda_runtime.h>
#include <math.h>

#define TWO_B 128
#define KCH   256
#define MSZ   512
#define DIM   256
#define NROWS (TWO_B * KCH)   // 32768
#define EPSN  1e-8f

// Scratch: normalized rows, batch-major [b][i][d], pre-scaled by 1/sqrt(2)
__device__ float  g_zt[(size_t)TWO_B * MSZ * DIM];   // 64 MB
__device__ double g_pos;   // sum of cos over 32768 rows
__device__ double g_neg;   // sum of lse over 65536 rows

__global__ void init_kernel() {
    g_pos = 0.0;
    g_neg = 0.0;
}

// One warp per row: norms + cosine + write pre-scaled normalized rows batch-major.
__global__ void normalize_kernel(const float* __restrict__ x,
                                 const float* __restrict__ xp) {
    int wib  = threadIdx.x >> 5;                 // warp in block (0..7)
    int lane = threadIdx.x & 31;
    int row  = blockIdx.x * 8 + wib;             // 0..32767

    const float4* xr = (const float4*)(x  + (size_t)row * DIM);
    const float4* pr = (const float4*)(xp + (size_t)row * DIM);
    float4 xa = xr[lane], xb = xr[lane + 32];
    float4 pa = pr[lane], pb = pr[lane + 32];

    float ssx = xa.x*xa.x + xa.y*xa.y + xa.z*xa.z + xa.w*xa.w
              + xb.x*xb.x + xb.y*xb.y + xb.z*xb.z + xb.w*xb.w;
    float ssp = pa.x*pa.x + pa.y*pa.y + pa.z*pa.z + pa.w*pa.w
              + pb.x*pb.x + pb.y*pb.y + pb.z*pb.z + pb.w*pb.w;
    float dt  = xa.x*pa.x + xa.y*pa.y + xa.z*pa.z + xa.w*pa.w
              + xb.x*pb.x + xb.y*pb.y + xb.z*pb.z + xb.w*pb.w;

    #pragma unroll
    for (int o = 16; o > 0; o >>= 1) {
        ssx += __shfl_down_sync(0xffffffffu, ssx, o);
        ssp += __shfl_down_sync(0xffffffffu, ssp, o);
        dt  += __shfl_down_sync(0xffffffffu, dt,  o);
    }
    ssx = __shfl_sync(0xffffffffu, ssx, 0);
    ssp = __shfl_sync(0xffffffffu, ssp, 0);
    dt  = __shfl_sync(0xffffffffu, dt,  0);

    float nx = fmaxf(sqrtf(ssx), EPSN);
    float np = fmaxf(sqrtf(ssp), EPSN);
    float cosv = dt / (nx * np);

    // write pre-scaled normalized rows
    const float RSQRT2 = 0.70710678118654752f;
    float sx = RSQRT2 / nx;
    float sp = RSQRT2 / np;
    int b = row & (TWO_B - 1);
    int i = row >> 7;
    float4* zx = (float4*)(g_zt + ((size_t)b * MSZ + i)       * DIM);
    float4* zp = (float4*)(g_zt + ((size_t)b * MSZ + i + KCH) * DIM);
    float4 oa = make_float4(xa.x*sx, xa.y*sx, xa.z*sx, xa.w*sx);
    float4 ob = make_float4(xb.x*sx, xb.y*sx, xb.z*sx, xb.w*sx);
    float4 qa = make_float4(pa.x*sp, pa.y*sp, pa.z*sp, pa.w*sp);
    float4 qb = make_float4(pb.x*sp, pb.y*sp, pb.z*sp, pb.w*sp);
    zx[lane]      = oa;
    zx[lane + 32] = ob;
    zp[lane]      = qa;
    zp[lane + 32] = qb;

    __shared__ float psum[8];
    if (lane == 0) psum[wib] = cosv;
    __syncthreads();
    if (threadIdx.x == 0) {
        float s = 0.f;
        #pragma unroll
        for (int q = 0; q < 8; q++) s += psum[q];
        atomicAdd(&g_pos, (double)s);
    }
}

// exp(u) for |u| <= ~0.5 via degree-7 Taylor (rel err ~1e-7)
__device__ __forceinline__ float exp_small(float u) {
    float p = 1.9841270e-4f;                 // 1/5040
    p = fmaf(p, u, 1.3888889e-3f);           // 1/720
    p = fmaf(p, u, 8.3333333e-3f);           // 1/120
    p = fmaf(p, u, 4.1666667e-2f);           // 1/24
    p = fmaf(p, u, 1.6666667e-1f);           // 1/6
    p = fmaf(p, u, 0.5f);
    p = fmaf(p, u, 1.0f);
    p = fmaf(p, u, 1.0f);                    // 1 + u + u^2*q
    return p;
}

#define TI 128
#define TJ 128
#define KC 32

// Per (b, i-tile): S = Z_tile @ Z^T, exp^4, masked row sums, log, accumulate.
__global__ __launch_bounds__(256, 2) void gram_kernel() {
    __shared__ float As[KC][TI + 4];    // [k][i], pad to 132
    __shared__ float Bs[KC][TJ + 4];
    __shared__ float red[TI][17];

    int b  = blockIdx.y;
    int i0 = blockIdx.x * TI;
    const float* Z = g_zt + (size_t)b * MSZ * DIM;

    int t  = threadIdx.x;
    int tx = t & 15;
    int ty = t >> 4;

    float rowpart[8];
    #pragma unroll
    for (int r = 0; r < 8; r++) rowpart[r] = 0.f;

    for (int jt = 0; jt < MSZ / TJ; jt++) {
        int j0 = jt * TJ;
        float C[8][8];
        #pragma unroll
        for (int r = 0; r < 8; r++)
            #pragma unroll
            for (int c = 0; c < 8; c++) C[r][c] = 0.f;

        for (int k0 = 0; k0 < DIM; k0 += KC) {
            // load 128x32 tiles of A (rows i0..) and B (rows j0..), store transposed
            #pragma unroll
            for (int q = 0; q < 4; q++) {
                int f  = t + q * 256;        // 0..1023
                int i  = f >> 3;
                int kq = f & 7;
                float4 v = *(const float4*)(Z + (size_t)(i0 + i) * DIM + k0 + kq * 4);
                As[kq*4+0][i] = v.x; As[kq*4+1][i] = v.y;
                As[kq*4+2][i] = v.z; As[kq*4+3][i] = v.w;
                float4 w = *(const float4*)(Z + (size_t)(j0 + i) * DIM + k0 + kq * 4);
                Bs[kq*4+0][i] = w.x; Bs[kq*4+1][i] = w.y;
                Bs[kq*4+2][i] = w.z; Bs[kq*4+3][i] = w.w;
            }
            __syncthreads();

            #pragma unroll
            for (int k = 0; k < KC; k++) {
                float a[8], bb[8];
                *(float4*)(a)      = *(const float4*)&As[k][ty * 8];
                *(float4*)(a + 4)  = *(const float4*)&As[k][ty * 8 + 4];
                *(float4*)(bb)     = *(const float4*)&Bs[k][tx * 8];
                *(float4*)(bb + 4) = *(const float4*)&Bs[k][tx * 8 + 4];
                #pragma unroll
                for (int r = 0; r < 8; r++)
                    #pragma unroll
                    for (int c = 0; c < 8; c++)
                        C[r][c] = fmaf(a[r], bb[c], C[r][c]);
            }
            __syncthreads();
        }

        // exp(4u) = (exp u)^4, skip diagonal
        #pragma unroll
        for (int r = 0; r < 8; r++) {
            int gi = i0 + ty * 8 + r;
            float acc = 0.f;
            #pragma unroll
            for (int c = 0; c < 8; c++) {
                int gj = j0 + tx * 8 + c;
                float e = exp_small(C[r][c]);
                e *= e;
                e *= e;
                acc += (gi == gj) ? 0.f : e;
            }
            rowpart[r] += acc;
        }
    }

    // reduce row partials across the 16 tx threads per row
    #pragma unroll
    for (int r = 0; r < 8; r++) red[ty * 8 + r][tx] = rowpart[r];
    __syncthreads();

    __shared__ float warpsum[4];
    if (t < TI) {
        float s = 0.f;
        #pragma unroll
        for (int q = 0; q < 16; q++) s += red[t][q];
        float lse = logf(s);
        #pragma unroll
        for (int o = 16; o > 0; o >>= 1)
            lse += __shfl_down_sync(0xffffffffu, lse, o);
        if ((t & 31) == 0) warpsum[t >> 5] = lse;
    }
    __syncthreads();
    if (t == 0) {
        float s = warpsum[0] + warpsum[1] + warpsum[2] + warpsum[3];
        atomicAdd(&g_neg, (double)s);
    }
}

__global__ void final_kernel(float* out) {
    double loss_neg = g_neg / (double)(TWO_B * MSZ);           // mean over 65536
    double loss_pos = (g_pos / (double)NROWS) * 2.0;           // mean(cos)/TEMP
    out[0] = (float)(loss_neg - loss_pos);
}

extern "C" void kernel_launch(void* const* d_in, const int* in_sizes, int n_in,
                              void* d_out, int out_size) {
    const float* x  = (const float*)d_in[0];
    const float* xp = (const float*)d_in[1];
    float* out = (float*)d_out;

    init_kernel<<<1, 1>>>();
    normalize_kernel<<<NROWS / 8, 256>>>(x, xp);
    dim3 grid(MSZ / TI, TWO_B);   // (4, 128)
    gram_kernel<<<grid, 256>>>();
    final_kernel<<<1, 1>>>(out);
}

// round 3
// speedup vs baseline: 4.7576x; 4.7576x over previous
#include <cuda_runtime.h>
#include <cuda_bf16.h>
#include <math.h>
#include <stdint.h>

#define TWO_B 128
#define KCH   256
#define MSZ   512
#define DIM   256
#define NROWS (TWO_B * KCH)   // 32768
#define EPSN  1e-8f

// bf16 normalized rows, batch-major [b][i][d], pre-scaled by 1/sqrt(2): 32 MB
__device__ __nv_bfloat16 g_zt[(size_t)TWO_B * MSZ * DIM];
__device__ double g_pos;
__device__ double g_neg;

// ---------------- helpers ----------------
__device__ __forceinline__ uint32_t smem_u32(const void* p) {
    uint32_t a;
    asm("{ .reg .u64 t; cvta.to.shared.u64 t, %1; cvt.u32.u64 %0, t; }"
        : "=r"(a) : "l"(p));
    return a;
}

#define CP_ASYNC16(sdst, gsrc) \
    asm volatile("cp.async.cg.shared.global [%0], [%1], 16;" \
                 :: "r"(sdst), "l"(gsrc) : "memory")
#define CP_COMMIT() asm volatile("cp.async.commit_group;" ::: "memory")
#define CP_WAIT0()  asm volatile("cp.async.wait_group 0;" ::: "memory")

#define LDMATRIX_X4(r, addr) \
    asm volatile("ldmatrix.sync.aligned.m8n8.x4.shared.b16 {%0,%1,%2,%3}, [%4];" \
                 : "=r"((r)[0]), "=r"((r)[1]), "=r"((r)[2]), "=r"((r)[3]) \
                 : "r"(addr))

#define MMA_BF16(c, a, b0, b1) \
    asm volatile("mma.sync.aligned.m16n8k16.row.col.f32.bf16.bf16.f32 " \
                 "{%0,%1,%2,%3},{%4,%5,%6,%7},{%8,%9},{%0,%1,%2,%3};" \
                 : "+f"((c)[0]), "+f"((c)[1]), "+f"((c)[2]), "+f"((c)[3]) \
                 : "r"((a)[0]), "r"((a)[1]), "r"((a)[2]), "r"((a)[3]), \
                   "r"(b0), "r"(b1))

// Tile: 128 rows x 256 bf16 (512B/row). Swizzled smem offset for (row, cb)
// where cb = 16-byte column index 0..31. XOR row bits into cb bits 0..2 so
// ldmatrix (8 rows, same cb) hits 8 distinct bank groups.
__device__ __forceinline__ uint32_t swz(uint32_t r, uint32_t cb) {
    return r * 512u + ((cb ^ (r & 7u)) << 4);
}

// ---------------- kernels ----------------
__global__ void init_kernel() { g_pos = 0.0; g_neg = 0.0; }

__device__ __forceinline__ uint32_t pack_bf2(float a, float b) {
    __nv_bfloat162 h = __floats2bfloat162_rn(a, b);
    return *reinterpret_cast<uint32_t*>(&h);
}

// One warp per row: norms + cosine; write pre-scaled normalized bf16 rows batch-major.
__global__ void normalize_kernel(const float* __restrict__ x,
                                 const float* __restrict__ xp) {
    int wib  = threadIdx.x >> 5;
    int lane = threadIdx.x & 31;
    int row  = blockIdx.x * 8 + wib;

    const float4* xr = (const float4*)(x  + (size_t)row * DIM);
    const float4* pr = (const float4*)(xp + (size_t)row * DIM);
    float4 xa = xr[lane], xb = xr[lane + 32];
    float4 pa = pr[lane], pb = pr[lane + 32];

    float ssx = xa.x*xa.x + xa.y*xa.y + xa.z*xa.z + xa.w*xa.w
              + xb.x*xb.x + xb.y*xb.y + xb.z*xb.z + xb.w*xb.w;
    float ssp = pa.x*pa.x + pa.y*pa.y + pa.z*pa.z + pa.w*pa.w
              + pb.x*pb.x + pb.y*pb.y + pb.z*pb.z + pb.w*pb.w;
    float dt  = xa.x*pa.x + xa.y*pa.y + xa.z*pa.z + xa.w*pa.w
              + xb.x*pb.x + xb.y*pb.y + xb.z*pb.z + xb.w*pb.w;

    #pragma unroll
    for (int o = 16; o > 0; o >>= 1) {
        ssx += __shfl_down_sync(0xffffffffu, ssx, o);
        ssp += __shfl_down_sync(0xffffffffu, ssp, o);
        dt  += __shfl_down_sync(0xffffffffu, dt,  o);
    }
    ssx = __shfl_sync(0xffffffffu, ssx, 0);
    ssp = __shfl_sync(0xffffffffu, ssp, 0);
    dt  = __shfl_sync(0xffffffffu, dt,  0);

    float nx = fmaxf(sqrtf(ssx), EPSN);
    float np = fmaxf(sqrtf(ssp), EPSN);
    float cosv = dt / (nx * np);

    const float RSQRT2 = 0.70710678118654752f;
    float sx = RSQRT2 / nx;
    float sp = RSQRT2 / np;
    int b = row & (TWO_B - 1);
    int i = row >> 7;

    uint2* zx = (uint2*)(g_zt + ((size_t)b * MSZ + i)       * DIM);
    uint2* zp = (uint2*)(g_zt + ((size_t)b * MSZ + i + KCH) * DIM);
    uint2 wa, wb2, qa, qb;
    wa.x  = pack_bf2(xa.x*sx, xa.y*sx); wa.y  = pack_bf2(xa.z*sx, xa.w*sx);
    wb2.x = pack_bf2(xb.x*sx, xb.y*sx); wb2.y = pack_bf2(xb.z*sx, xb.w*sx);
    qa.x  = pack_bf2(pa.x*sp, pa.y*sp); qa.y  = pack_bf2(pa.z*sp, pa.w*sp);
    qb.x  = pack_bf2(pb.x*sp, pb.y*sp); qb.y  = pack_bf2(pb.z*sp, pb.w*sp);
    zx[lane] = wa; zx[lane + 32] = wb2;
    zp[lane] = qa; zp[lane + 32] = qb;

    __shared__ float psum[8];
    if (lane == 0) psum[wib] = cosv;
    __syncthreads();
    if (threadIdx.x == 0) {
        float s = 0.f;
        #pragma unroll
        for (int q = 0; q < 8; q++) s += psum[q];
        atomicAdd(&g_pos, (double)s);
    }
}

// exp(u) for |u| <= ~0.5: degree-7 Taylor, rel err ~1e-7
__device__ __forceinline__ float exp_small(float u) {
    float p = 1.9841270e-4f;
    p = fmaf(p, u, 1.3888889e-3f);
    p = fmaf(p, u, 8.3333333e-3f);
    p = fmaf(p, u, 4.1666667e-2f);
    p = fmaf(p, u, 1.6666667e-1f);
    p = fmaf(p, u, 0.5f);
    p = fmaf(p, u, 1.0f);
    p = fmaf(p, u, 1.0f);
    return p;
}

// Copy one 128x256 bf16 tile (64KB) gmem -> swizzled smem via cp.async.
// 4096 16B chunks, 256 threads -> 16 per thread.
__device__ __forceinline__ void tile_cp(uint32_t sdst, const __nv_bfloat16* src,
                                        int t) {
    const char* g = (const char*)src;
    #pragma unroll
    for (int q = 0; q < 16; q++) {
        int f = t + q * 256;
        uint32_t r = f >> 5, cb = f & 31;
        CP_ASYNC16(sdst + swz(r, cb), g + (size_t)f * 16);
    }
}

// Per (b, i-tile): D = A @ B^T via mma.sync bf16; epilogue exp^4 + masked rowsum.
__global__ __launch_bounds__(256, 1) void gram_kernel() {
    __shared__ float red[128][5];
    __shared__ float warpsum[4];
    extern __shared__ char dyn[];

    int t    = threadIdx.x;
    int wid  = t >> 5;
    int lane = t & 31;
    int b    = blockIdx.y;
    int i0   = blockIdx.x * 128;

    int wm = wid >> 2;          // 0..1 : warp m-offset = wm*64
    int wn = wid & 3;           // 0..3 : warp n-offset = wn*32

    uint32_t sA = smem_u32(dyn);
    uint32_t sB[2] = { sA + 65536, sA + 131072 };

    const __nv_bfloat16* Z = g_zt + (size_t)b * MSZ * DIM;

    // prologue: A tile (rows i0..) + B tile 0 (rows 0..127)
    tile_cp(sA, Z + (size_t)i0 * DIM, t);
    tile_cp(sB[0], Z, t);
    CP_COMMIT();
    CP_WAIT0();
    __syncthreads();

    float rowacc[8];
    #pragma unroll
    for (int q = 0; q < 8; q++) rowacc[q] = 0.f;

    for (int jt = 0; jt < 4; jt++) {
        if (jt < 3) {
            tile_cp(sB[(jt + 1) & 1], Z + (size_t)(jt + 1) * 128 * DIM, t);
            CP_COMMIT();
        }

        float C[4][4][4];
        #pragma unroll
        for (int mt = 0; mt < 4; mt++)
            #pragma unroll
            for (int nt = 0; nt < 4; nt++)
                #pragma unroll
                for (int e = 0; e < 4; e++) C[mt][nt][e] = 0.f;

        uint32_t sBj = sB[jt & 1];
        #pragma unroll 2
        for (int k = 0; k < 16; k++) {
            uint32_t cb = 2u * k + (lane >> 4);
            uint32_t afr[4][4], bfr[2][4];
            #pragma unroll
            for (int mt = 0; mt < 4; mt++) {
                uint32_t r = wm * 64 + mt * 16 + (lane & 15);
                LDMATRIX_X4(afr[mt], sA + swz(r, cb));
            }
            #pragma unroll
            for (int h = 0; h < 2; h++) {
                uint32_t r = wn * 32 + h * 16 + (lane & 15);
                LDMATRIX_X4(bfr[h], sBj + swz(r, cb));
            }
            #pragma unroll
            for (int mt = 0; mt < 4; mt++)
                #pragma unroll
                for (int nt = 0; nt < 4; nt++) {
                    uint32_t b0 = bfr[nt >> 1][(nt & 1) ? 1 : 0];
                    uint32_t b1 = bfr[nt >> 1][(nt & 1) ? 3 : 2];
                    MMA_BF16(C[mt][nt], afr[mt], b0, b1);
                }
        }

        // epilogue: exp(4u) = exp_small(u)^4, mask diagonal, accumulate per-row
        int j0 = jt * 128;
        #pragma unroll
        for (int mt = 0; mt < 4; mt++) {
            #pragma unroll
            for (int h = 0; h < 2; h++) {
                int gi = i0 + wm * 64 + mt * 16 + (lane >> 2) + 8 * h;
                float acc = 0.f;
                #pragma unroll
                for (int nt = 0; nt < 4; nt++) {
                    #pragma unroll
                    for (int e = 0; e < 2; e++) {
                        float u = C[mt][nt][h * 2 + e];
                        float ex = exp_small(u);
                        ex *= ex;
                        ex *= ex;
                        int gj = j0 + wn * 32 + nt * 8 + (lane & 3) * 2 + e;
                        acc += (gi == gj) ? 0.f : ex;
                    }
                }
                rowacc[mt * 2 + h] += acc;
            }
        }

        CP_WAIT0();
        __syncthreads();
    }

    // reduce the 4 threads sharing each row (lane&3), then across wn via smem
    #pragma unroll
    for (int q = 0; q < 8; q++) {
        rowacc[q] += __shfl_xor_sync(0xffffffffu, rowacc[q], 1);
        rowacc[q] += __shfl_xor_sync(0xffffffffu, rowacc[q], 2);
    }
    if ((lane & 3) == 0) {
        #pragma unroll
        for (int mt = 0; mt < 4; mt++)
            #pragma unroll
            for (int h = 0; h < 2; h++)
                red[wm * 64 + mt * 16 + (lane >> 2) + 8 * h][wn] =
                    rowacc[mt * 2 + h];
    }
    __syncthreads();

    if (t < 128) {
        float s = red[t][0] + red[t][1] + red[t][2] + red[t][3];
        float l = logf(s);
        #pragma unroll
        for (int o = 16; o > 0; o >>= 1)
            l += __shfl_down_sync(0xffffffffu, l, o);
        if ((t & 31) == 0) warpsum[t >> 5] = l;
    }
    __syncthreads();
    if (t == 0)
        atomicAdd(&g_neg, (double)(warpsum[0] + warpsum[1] + warpsum[2] + warpsum[3]));
}

__global__ void final_kernel(float* out) {
    double loss_neg = g_neg / (double)(TWO_B * MSZ);
    double loss_pos = (g_pos / (double)NROWS) * 2.0;
    out[0] = (float)(loss_neg - loss_pos);
}

extern "C" void kernel_launch(void* const* d_in, const int* in_sizes, int n_in,
                              void* d_out, int out_size) {
    const float* x  = (const float*)d_in[0];
    const float* xp = (const float*)d_in[1];
    float* out = (float*)d_out;

    cudaFuncSetAttribute(gram_kernel,
                         cudaFuncAttributeMaxDynamicSharedMemorySize, 196608);

    init_kernel<<<1, 1>>>();
    normalize_kernel<<<NROWS / 8, 256>>>(x, xp);
    dim3 grid(MSZ / 128, TWO_B);   // (4, 128)
    gram_kernel<<<grid, 256, 196608>>>();
    final_kernel<<<1, 1>>>(out);
}

// round 4
// speedup vs baseline: 6.9793x; 1.4670x over previous
#include <cuda_runtime.h>
#include <cuda_bf16.h>
#include <math.h>
#include <stdint.h>

#define TWO_B 128
#define KCH   256
#define MSZ   512
#define DIM   256
#define NROWS (TWO_B * KCH)   // 32768
#define EPSN  1e-8f

// bf16 normalized rows, batch-major [b][i][d], pre-scaled by 1/sqrt(2): 32 MB
__device__ __nv_bfloat16 g_zt[(size_t)TWO_B * MSZ * DIM];
// per-row exp-sum partials: [b][row_tile][slot][row_in_tile], each written once
__device__ float g_rowpart[TWO_B][4][4][128];     // 1 MB
__device__ float g_pos_part[NROWS / 8];           // per normalize block
__device__ float g_neg_part[TWO_B];               // per-batch lse sums

__constant__ int TI_LUT[10] = {0,0,0,0,1,1,1,2,2,3};
__constant__ int TJ_LUT[10] = {0,1,2,3,1,2,3,2,3,3};

// ---------------- helpers ----------------
__device__ __forceinline__ uint32_t smem_u32(const void* p) {
    uint32_t a;
    asm("{ .reg .u64 t; cvta.to.shared.u64 t, %1; cvt.u32.u64 %0, t; }"
        : "=r"(a) : "l"(p));
    return a;
}

#define CP_ASYNC16(sdst, gsrc) \
    asm volatile("cp.async.cg.shared.global [%0], [%1], 16;" \
                 :: "r"(sdst), "l"(gsrc) : "memory")
#define CP_COMMIT() asm volatile("cp.async.commit_group;" ::: "memory")
#define CP_WAIT0()  asm volatile("cp.async.wait_group 0;" ::: "memory")

#define LDMATRIX_X4(r, addr) \
    asm volatile("ldmatrix.sync.aligned.m8n8.x4.shared.b16 {%0,%1,%2,%3}, [%4];" \
                 : "=r"((r)[0]), "=r"((r)[1]), "=r"((r)[2]), "=r"((r)[3]) \
                 : "r"(addr))

#define MMA_BF16(c, a, b0, b1) \
    asm volatile("mma.sync.aligned.m16n8k16.row.col.f32.bf16.bf16.f32 " \
                 "{%0,%1,%2,%3},{%4,%5,%6,%7},{%8,%9},{%0,%1,%2,%3};" \
                 : "+f"((c)[0]), "+f"((c)[1]), "+f"((c)[2]), "+f"((c)[3]) \
                 : "r"((a)[0]), "r"((a)[1]), "r"((a)[2]), "r"((a)[3]), \
                   "r"(b0), "r"(b1))

// 128 rows x 256 bf16 tile (512B/row); cb = 16B column 0..31, XOR-swizzled
__device__ __forceinline__ uint32_t swz(uint32_t r, uint32_t cb) {
    return r * 512u + ((cb ^ (r & 7u)) << 4);
}

__device__ __forceinline__ uint32_t pack_bf2(float a, float b) {
    __nv_bfloat162 h = __floats2bfloat162_rn(a, b);
    return *reinterpret_cast<uint32_t*>(&h);
}

// exp(u) for |u| <= ~0.5: degree-7 Taylor, rel err ~1e-7
__device__ __forceinline__ float exp_small(float u) {
    float p = 1.9841270e-4f;
    p = fmaf(p, u, 1.3888889e-3f);
    p = fmaf(p, u, 8.3333333e-3f);
    p = fmaf(p, u, 4.1666667e-2f);
    p = fmaf(p, u, 1.6666667e-1f);
    p = fmaf(p, u, 0.5f);
    p = fmaf(p, u, 1.0f);
    p = fmaf(p, u, 1.0f);
    return p;
}

// ---------------- kernels ----------------
// One warp per row: norms + cosine; write pre-scaled normalized bf16 rows.
__global__ void normalize_kernel(const float* __restrict__ x,
                                 const float* __restrict__ xp) {
    int wib  = threadIdx.x >> 5;
    int lane = threadIdx.x & 31;
    int row  = blockIdx.x * 8 + wib;

    const float4* xr = (const float4*)(x  + (size_t)row * DIM);
    const float4* pr = (const float4*)(xp + (size_t)row * DIM);
    float4 xa = xr[lane], xb = xr[lane + 32];
    float4 pa = pr[lane], pb = pr[lane + 32];

    float ssx = xa.x*xa.x + xa.y*xa.y + xa.z*xa.z + xa.w*xa.w
              + xb.x*xb.x + xb.y*xb.y + xb.z*xb.z + xb.w*xb.w;
    float ssp = pa.x*pa.x + pa.y*pa.y + pa.z*pa.z + pa.w*pa.w
              + pb.x*pb.x + pb.y*pb.y + pb.z*pb.z + pb.w*pb.w;
    float dt  = xa.x*pa.x + xa.y*pa.y + xa.z*pa.z + xa.w*pa.w
              + xb.x*pb.x + xb.y*pb.y + xb.z*pb.z + xb.w*pb.w;

    #pragma unroll
    for (int o = 16; o > 0; o >>= 1) {
        ssx += __shfl_down_sync(0xffffffffu, ssx, o);
        ssp += __shfl_down_sync(0xffffffffu, ssp, o);
        dt  += __shfl_down_sync(0xffffffffu, dt,  o);
    }
    ssx = __shfl_sync(0xffffffffu, ssx, 0);
    ssp = __shfl_sync(0xffffffffu, ssp, 0);
    dt  = __shfl_sync(0xffffffffu, dt,  0);

    float nx = fmaxf(sqrtf(ssx), EPSN);
    float np = fmaxf(sqrtf(ssp), EPSN);
    float cosv = dt / (nx * np);

    const float RSQRT2 = 0.70710678118654752f;
    float sx = RSQRT2 / nx;
    float sp = RSQRT2 / np;
    int b = row & (TWO_B - 1);
    int i = row >> 7;

    uint2* zx = (uint2*)(g_zt + ((size_t)b * MSZ + i)       * DIM);
    uint2* zp = (uint2*)(g_zt + ((size_t)b * MSZ + i + KCH) * DIM);
    uint2 wa, wb2, qa, qb;
    wa.x  = pack_bf2(xa.x*sx, xa.y*sx); wa.y  = pack_bf2(xa.z*sx, xa.w*sx);
    wb2.x = pack_bf2(xb.x*sx, xb.y*sx); wb2.y = pack_bf2(xb.z*sx, xb.w*sx);
    qa.x  = pack_bf2(pa.x*sp, pa.y*sp); qa.y  = pack_bf2(pa.z*sp, pa.w*sp);
    qb.x  = pack_bf2(pb.x*sp, pb.y*sp); qb.y  = pack_bf2(pb.z*sp, pb.w*sp);
    zx[lane] = wa; zx[lane + 32] = wb2;
    zp[lane] = qa; zp[lane + 32] = qb;

    __shared__ float psum[8];
    if (lane == 0) psum[wib] = cosv;
    __syncthreads();
    if (threadIdx.x == 0) {
        float s = 0.f;
        #pragma unroll
        for (int q = 0; q < 8; q++) s += psum[q];
        g_pos_part[blockIdx.x] = s;
    }
}

// One CTA = one (b, ti<=tj) tile pair. S = A_i @ A_j^T, exp^4, row+col sums.
__global__ __launch_bounds__(256, 1) void gram_kernel() {
    __shared__ float red[128][4];
    __shared__ float colred[128][2];
    extern __shared__ char dyn[];

    int t    = threadIdx.x;
    int wid  = t >> 5;
    int lane = t & 31;
    int b    = blockIdx.y;
    int p    = blockIdx.x;
    int ti   = TI_LUT[p];
    int tj   = TJ_LUT[p];
    bool diag = (ti == tj);

    int wm = wid >> 2;          // 0..1 : warp m-offset = wm*64
    int wn = wid & 3;           // 0..3 : warp n-offset = wn*32

    uint32_t sA = smem_u32(dyn);
    uint32_t sBj = diag ? sA : (sA + 65536);

    const __nv_bfloat16* Z = g_zt + (size_t)b * MSZ * DIM;
    {   // load tiles (A always; B only if off-diagonal)
        const char* gA = (const char*)(Z + (size_t)ti * 128 * DIM);
        const char* gB = (const char*)(Z + (size_t)tj * 128 * DIM);
        #pragma unroll
        for (int q = 0; q < 16; q++) {
            int f = t + q * 256;
            uint32_t off = swz(f >> 5, f & 31);
            CP_ASYNC16(sA + off, gA + (size_t)f * 16);
            if (!diag) CP_ASYNC16(sBj + off, gB + (size_t)f * 16);
        }
        CP_COMMIT();
        CP_WAIT0();
        __syncthreads();
    }

    float C[4][4][4];
    #pragma unroll
    for (int mt = 0; mt < 4; mt++)
        #pragma unroll
        for (int nt = 0; nt < 4; nt++)
            #pragma unroll
            for (int e = 0; e < 4; e++) C[mt][nt][e] = 0.f;

    #pragma unroll 2
    for (int k = 0; k < 16; k++) {
        uint32_t cb = 2u * k + (lane >> 4);
        uint32_t afr[4][4], bfr[2][4];
        #pragma unroll
        for (int mt = 0; mt < 4; mt++) {
            uint32_t r = wm * 64 + mt * 16 + (lane & 15);
            LDMATRIX_X4(afr[mt], sA + swz(r, cb));
        }
        #pragma unroll
        for (int h = 0; h < 2; h++) {
            uint32_t r = wn * 32 + h * 16 + (lane & 15);
            LDMATRIX_X4(bfr[h], sBj + swz(r, cb));
        }
        #pragma unroll
        for (int mt = 0; mt < 4; mt++)
            #pragma unroll
            for (int nt = 0; nt < 4; nt++) {
                uint32_t b0 = bfr[nt >> 1][(nt & 1) ? 1 : 0];
                uint32_t b1 = bfr[nt >> 1][(nt & 1) ? 3 : 2];
                MMA_BF16(C[mt][nt], afr[mt], b0, b1);
            }
    }

    // epilogue: e = exp(4u), mask diagonal, row sums + col sums
    float rowacc[8], colacc[8];
    #pragma unroll
    for (int q = 0; q < 8; q++) { rowacc[q] = 0.f; colacc[q] = 0.f; }

    int i0 = ti * 128, j0 = tj * 128;
    #pragma unroll
    for (int mt = 0; mt < 4; mt++) {
        #pragma unroll
        for (int h = 0; h < 2; h++) {
            int gi = i0 + wm * 64 + mt * 16 + (lane >> 2) + 8 * h;
            #pragma unroll
            for (int nt = 0; nt < 4; nt++) {
                #pragma unroll
                for (int e = 0; e < 2; e++) {
                    float u = C[mt][nt][h * 2 + e];
                    float ex = exp_small(u);
                    ex *= ex;
                    ex *= ex;
                    int gj = j0 + wn * 32 + nt * 8 + (lane & 3) * 2 + e;
                    ex = (gi == gj) ? 0.f : ex;
                    rowacc[mt * 2 + h] += ex;
                    colacc[nt * 2 + e] += ex;
                }
            }
        }
    }

    // row reduction: over lane&3 (4 threads share a row), then over wn via smem
    #pragma unroll
    for (int q = 0; q < 8; q++) {
        rowacc[q] += __shfl_xor_sync(0xffffffffu, rowacc[q], 1);
        rowacc[q] += __shfl_xor_sync(0xffffffffu, rowacc[q], 2);
    }
    if ((lane & 3) == 0) {
        #pragma unroll
        for (int mt = 0; mt < 4; mt++)
            #pragma unroll
            for (int h = 0; h < 2; h++)
                red[wm * 64 + mt * 16 + (lane >> 2) + 8 * h][wn] =
                    rowacc[mt * 2 + h];
    }

    // col reduction (off-diag only): over lane>>2 (8 row-groups), then over wm
    if (!diag) {
        #pragma unroll
        for (int q = 0; q < 8; q++) {
            colacc[q] += __shfl_xor_sync(0xffffffffu, colacc[q], 4);
            colacc[q] += __shfl_xor_sync(0xffffffffu, colacc[q], 8);
            colacc[q] += __shfl_xor_sync(0xffffffffu, colacc[q], 16);
        }
        if (lane < 4) {
            #pragma unroll
            for (int nt = 0; nt < 4; nt++)
                #pragma unroll
                for (int e = 0; e < 2; e++)
                    colred[wn * 32 + nt * 8 + lane * 2 + e][wm] =
                        colacc[nt * 2 + e];
        }
    }
    __syncthreads();

    if (t < 128) {
        g_rowpart[b][ti][tj][t] = red[t][0] + red[t][1] + red[t][2] + red[t][3];
        if (!diag)
            g_rowpart[b][tj][ti][t] = colred[t][0] + colred[t][1];
    }
}

// One block per batch: 512 rows, sum 4 partials, log, reduce.
__global__ void lse_kernel() {
    int b = blockIdx.x;
    int t = threadIdx.x;           // 0..511
    int tr = t >> 7, r = t & 127;
    float s = g_rowpart[b][tr][0][r] + g_rowpart[b][tr][1][r]
            + g_rowpart[b][tr][2][r] + g_rowpart[b][tr][3][r];
    float l = logf(s);

    __shared__ float wsum[16];
    #pragma unroll
    for (int o = 16; o > 0; o >>= 1)
        l += __shfl_down_sync(0xffffffffu, l, o);
    if ((t & 31) == 0) wsum[t >> 5] = l;
    __syncthreads();
    if (t == 0) {
        float acc = 0.f;
        #pragma unroll
        for (int q = 0; q < 16; q++) acc += wsum[q];
        g_neg_part[b] = acc;
    }
}

__global__ void final_kernel(float* out) {
    int t = threadIdx.x;           // 256 threads
    float ps = 0.f;
    #pragma unroll
    for (int q = 0; q < 16; q++) ps += g_pos_part[t + q * 256];
    float ns = (t < TWO_B) ? g_neg_part[t] : 0.f;

    __shared__ double wp[8], wn_[8];
    double dp = (double)ps, dn = (double)ns;
    #pragma unroll
    for (int o = 16; o > 0; o >>= 1) {
        dp += __shfl_down_sync(0xffffffffu, dp, o);
        dn += __shfl_down_sync(0xffffffffu, dn, o);
    }
    if ((t & 31) == 0) { wp[t >> 5] = dp; wn_[t >> 5] = dn; }
    __syncthreads();
    if (t == 0) {
        double sp = 0.0, sn = 0.0;
        #pragma unroll
        for (int q = 0; q < 8; q++) { sp += wp[q]; sn += wn_[q]; }
        double loss_neg = sn / (double)(TWO_B * MSZ);
        double loss_pos = (sp / (double)NROWS) * 2.0;
        out[0] = (float)(loss_neg - loss_pos);
    }
}

extern "C" void kernel_launch(void* const* d_in, const int* in_sizes, int n_in,
                              void* d_out, int out_size) {
    const float* x  = (const float*)d_in[0];
    const float* xp = (const float*)d_in[1];
    float* out = (float*)d_out;

    cudaFuncSetAttribute(gram_kernel,
                         cudaFuncAttributeMaxDynamicSharedMemorySize, 131072);

    normalize_kernel<<<NROWS / 8, 256>>>(x, xp);
    dim3 grid(10, TWO_B);   // 10 tile pairs x 128 batches
    gram_kernel<<<grid, 256, 131072>>>();
    lse_kernel<<<TWO_B, 512>>>();
    final_kernel<<<1, 256>>>(out);
}

// round 5
// speedup vs baseline: 8.0022x; 1.1466x over previous
#include <cuda_runtime.h>
#include <cuda_bf16.h>
#include <cuda_fp8.h>
#include <math.h>
#include <stdint.h>

#define TWO_B 128
#define KCH   256
#define MSZ   512
#define DIM   256
#define NROWS (TWO_B * KCH)   // 32768
#define EPSN  1e-8f

// fp8 normalized rows, batch-major [b][i][d], scaled by 16/sqrt(2): 16 MB
__device__ uint8_t g_z8[(size_t)TWO_B * MSZ * DIM];
// per-row exp-sum partials: [b][row_tile][slot][row_in_tile], each written once
__device__ float g_rowpart[TWO_B][4][4][128];
__device__ float g_pos_part[NROWS / 8];
__device__ float g_neg_part[TWO_B];
__device__ unsigned g_ctr;

__constant__ int TI_LUT[10] = {0,0,0,0,1,1,1,2,2,3};
__constant__ int TJ_LUT[10] = {0,1,2,3,1,2,3,2,3,3};

// ---------------- helpers ----------------
__device__ __forceinline__ uint32_t smem_u32(const void* p) {
    uint32_t a;
    asm("{ .reg .u64 t; cvta.to.shared.u64 t, %1; cvt.u32.u64 %0, t; }"
        : "=r"(a) : "l"(p));
    return a;
}

#define CP_ASYNC16(sdst, gsrc) \
    asm volatile("cp.async.cg.shared.global [%0], [%1], 16;" \
                 :: "r"(sdst), "l"(gsrc) : "memory")
#define CP_COMMIT() asm volatile("cp.async.commit_group;" ::: "memory")
#define CP_WAIT0()  asm volatile("cp.async.wait_group 0;" ::: "memory")

#define LDMATRIX_X4(r, addr) \
    asm volatile("ldmatrix.sync.aligned.m8n8.x4.shared.b16 {%0,%1,%2,%3}, [%4];" \
                 : "=r"((r)[0]), "=r"((r)[1]), "=r"((r)[2]), "=r"((r)[3]) \
                 : "r"(addr))

#define MMA_FP8(c, a, b0, b1) \
    asm volatile("mma.sync.aligned.m16n8k32.row.col.f32.e4m3.e4m3.f32 " \
                 "{%0,%1,%2,%3},{%4,%5,%6,%7},{%8,%9},{%0,%1,%2,%3};" \
                 : "+f"((c)[0]), "+f"((c)[1]), "+f"((c)[2]), "+f"((c)[3]) \
                 : "r"((a)[0]), "r"((a)[1]), "r"((a)[2]), "r"((a)[3]), \
                   "r"(b0), "r"(b1))

// Tile: 128 rows x 256 fp8 (256B/row); cb = 16B column 0..15, XOR-swizzled
__device__ __forceinline__ uint32_t swz8(uint32_t r, uint32_t cb) {
    return r * 256u + ((cb ^ (r & 7u)) << 4);
}

__device__ __forceinline__ uint32_t pack_fp8x4(float a, float b, float c, float d) {
    __nv_fp8x2_storage_t lo = __nv_cvt_float2_to_fp8x2(make_float2(a, b),
                                                       __NV_SATFINITE, __NV_E4M3);
    __nv_fp8x2_storage_t hi = __nv_cvt_float2_to_fp8x2(make_float2(c, d),
                                                       __NV_SATFINITE, __NV_E4M3);
    return (uint32_t)lo | ((uint32_t)hi << 16);
}

// ---------------- kernels ----------------
// One warp per row: norms + cosine; write scaled normalized fp8 rows batch-major.
__global__ void normalize_kernel(const float* __restrict__ x,
                                 const float* __restrict__ xp) {
    if (blockIdx.x == 0 && threadIdx.x == 0) g_ctr = 0;

    int wib  = threadIdx.x >> 5;
    int lane = threadIdx.x & 31;
    int row  = blockIdx.x * 8 + wib;

    const float4* xr = (const float4*)(x  + (size_t)row * DIM);
    const float4* pr = (const float4*)(xp + (size_t)row * DIM);
    float4 xa = xr[lane], xb = xr[lane + 32];
    float4 pa = pr[lane], pb = pr[lane + 32];

    float ssx = xa.x*xa.x + xa.y*xa.y + xa.z*xa.z + xa.w*xa.w
              + xb.x*xb.x + xb.y*xb.y + xb.z*xb.z + xb.w*xb.w;
    float ssp = pa.x*pa.x + pa.y*pa.y + pa.z*pa.z + pa.w*pa.w
              + pb.x*pb.x + pb.y*pb.y + pb.z*pb.z + pb.w*pb.w;
    float dt  = xa.x*pa.x + xa.y*pa.y + xa.z*pa.z + xa.w*pa.w
              + xb.x*pb.x + xb.y*pb.y + xb.z*pb.z + xb.w*pb.w;

    #pragma unroll
    for (int o = 16; o > 0; o >>= 1) {
        ssx += __shfl_down_sync(0xffffffffu, ssx, o);
        ssp += __shfl_down_sync(0xffffffffu, ssp, o);
        dt  += __shfl_down_sync(0xffffffffu, dt,  o);
    }
    ssx = __shfl_sync(0xffffffffu, ssx, 0);
    ssp = __shfl_sync(0xffffffffu, ssp, 0);
    dt  = __shfl_sync(0xffffffffu, dt,  0);

    float nx = fmaxf(sqrtf(ssx), EPSN);
    float np = fmaxf(sqrtf(ssp), EPSN);
    float cosv = dt / (nx * np);

    // scale = 16/sqrt(2): dot of stored vectors = 256 * (cos/2)
    const float SCL = 11.313708498984761f;
    float sx = SCL / nx;
    float sp = SCL / np;
    int b = row & (TWO_B - 1);
    int i = row >> 7;

    uint8_t* zx = g_z8 + ((size_t)b * MSZ + i)       * DIM;
    uint8_t* zp = g_z8 + ((size_t)b * MSZ + i + KCH) * DIM;
    *(uint32_t*)(zx + 4 * lane)       = pack_fp8x4(xa.x*sx, xa.y*sx, xa.z*sx, xa.w*sx);
    *(uint32_t*)(zx + 128 + 4 * lane) = pack_fp8x4(xb.x*sx, xb.y*sx, xb.z*sx, xb.w*sx);
    *(uint32_t*)(zp + 4 * lane)       = pack_fp8x4(pa.x*sp, pa.y*sp, pa.z*sp, pa.w*sp);
    *(uint32_t*)(zp + 128 + 4 * lane) = pack_fp8x4(pb.x*sp, pb.y*sp, pb.z*sp, pb.w*sp);

    __shared__ float psum[8];
    if (lane == 0) psum[wib] = cosv;
    __syncthreads();
    if (threadIdx.x == 0) {
        float s = 0.f;
        #pragma unroll
        for (int q = 0; q < 8; q++) s += psum[q];
        g_pos_part[blockIdx.x] = s;
    }
}

// exp(c/256) for |c| <= 128 via degree-7 Taylor with pre-scaled coefficients
__device__ __forceinline__ float exp_scaled(float c) {
    float p = 2.7537436e-21f;                // (1/5040)*s^7, s=1/256
    p = fmaf(p, c, 4.9343246e-18f);          // (1/720)*s^6
    p = fmaf(p, c, 7.5791225e-15f);          // (1/120)*s^5
    p = fmaf(p, c, 9.7012768e-12f);          // (1/24)*s^4
    p = fmaf(p, c, 9.9341075e-9f);           // (1/6)*s^3
    p = fmaf(p, c, 7.6293945e-6f);           // (1/2)*s^2
    p = fmaf(p, c, 3.90625e-3f);             // s
    p = fmaf(p, c, 1.0f);
    return p;
}

// One CTA = one (b, ti<=tj) tile pair. S = A_i @ A_j^T (fp8), exp^4, row+col sums.
__global__ __launch_bounds__(256, 2) void gram_kernel() {
    __shared__ float red[128][4];
    __shared__ float colred[128][2];
    extern __shared__ char dyn[];

    int t    = threadIdx.x;
    int wid  = t >> 5;
    int lane = t & 31;
    int b    = blockIdx.y;
    int p    = blockIdx.x;
    int ti   = TI_LUT[p];
    int tj   = TJ_LUT[p];
    bool diag = (ti == tj);

    int wm = wid >> 2;          // 0..1 : warp m-offset = wm*64
    int wn = wid & 3;           // 0..3 : warp n-offset = wn*32

    uint32_t sA = smem_u32(dyn);
    uint32_t sBj = diag ? sA : (sA + 32768);

    const uint8_t* Z = g_z8 + (size_t)b * MSZ * DIM;
    {   // load tiles: 2048 16B chunks each (32KB)
        const char* gA = (const char*)(Z + (size_t)ti * 128 * DIM);
        const char* gB = (const char*)(Z + (size_t)tj * 128 * DIM);
        #pragma unroll
        for (int q = 0; q < 8; q++) {
            int f = t + q * 256;
            uint32_t off = swz8(f >> 4, f & 15);
            CP_ASYNC16(sA + off, gA + (size_t)f * 16);
            if (!diag) CP_ASYNC16(sBj + off, gB + (size_t)f * 16);
        }
        CP_COMMIT();
        CP_WAIT0();
        __syncthreads();
    }

    float C[4][4][4];
    #pragma unroll
    for (int mt = 0; mt < 4; mt++)
        #pragma unroll
        for (int nt = 0; nt < 4; nt++)
            #pragma unroll
            for (int e = 0; e < 4; e++) C[mt][nt][e] = 0.f;

    #pragma unroll
    for (int k = 0; k < 8; k++) {           // 8 steps of k=32 fp8
        uint32_t cb = 2u * k + (lane >> 4);
        uint32_t afr[4][4], bfr[2][4];
        #pragma unroll
        for (int mt = 0; mt < 4; mt++) {
            uint32_t r = wm * 64 + mt * 16 + (lane & 15);
            LDMATRIX_X4(afr[mt], sA + swz8(r, cb));
        }
        #pragma unroll
        for (int h = 0; h < 2; h++) {
            uint32_t r = wn * 32 + h * 16 + (lane & 15);
            LDMATRIX_X4(bfr[h], sBj + swz8(r, cb));
        }
        #pragma unroll
        for (int mt = 0; mt < 4; mt++)
            #pragma unroll
            for (int nt = 0; nt < 4; nt++) {
                uint32_t b0 = bfr[nt >> 1][(nt & 1) ? 1 : 0];
                uint32_t b1 = bfr[nt >> 1][(nt & 1) ? 3 : 2];
                MMA_FP8(C[mt][nt], afr[mt], b0, b1);
            }
    }

    // epilogue: e = exp(4*c/256)^... exp_scaled(c)^4 = exp(sim/TEMP)
    float rowacc[8], colacc[8];
    #pragma unroll
    for (int q = 0; q < 8; q++) { rowacc[q] = 0.f; colacc[q] = 0.f; }

    int i0 = ti * 128, j0 = tj * 128;
    #pragma unroll
    for (int mt = 0; mt < 4; mt++) {
        #pragma unroll
        for (int h = 0; h < 2; h++) {
            int gi = i0 + wm * 64 + mt * 16 + (lane >> 2) + 8 * h;
            #pragma unroll
            for (int nt = 0; nt < 4; nt++) {
                #pragma unroll
                for (int e = 0; e < 2; e++) {
                    float u = C[mt][nt][h * 2 + e];
                    float ex = exp_scaled(u);
                    ex *= ex;
                    ex *= ex;
                    int gj = j0 + wn * 32 + nt * 8 + (lane & 3) * 2 + e;
                    ex = (gi == gj) ? 0.f : ex;
                    rowacc[mt * 2 + h] += ex;
                    colacc[nt * 2 + e] += ex;
                }
            }
        }
    }

    // row reduction: over lane&3, then over wn via smem
    #pragma unroll
    for (int q = 0; q < 8; q++) {
        rowacc[q] += __shfl_xor_sync(0xffffffffu, rowacc[q], 1);
        rowacc[q] += __shfl_xor_sync(0xffffffffu, rowacc[q], 2);
    }
    if ((lane & 3) == 0) {
        #pragma unroll
        for (int mt = 0; mt < 4; mt++)
            #pragma unroll
            for (int h = 0; h < 2; h++)
                red[wm * 64 + mt * 16 + (lane >> 2) + 8 * h][wn] =
                    rowacc[mt * 2 + h];
    }

    // col reduction (off-diag only): over lane>>2, then over wm
    if (!diag) {
        #pragma unroll
        for (int q = 0; q < 8; q++) {
            colacc[q] += __shfl_xor_sync(0xffffffffu, colacc[q], 4);
            colacc[q] += __shfl_xor_sync(0xffffffffu, colacc[q], 8);
            colacc[q] += __shfl_xor_sync(0xffffffffu, colacc[q], 16);
        }
        if (lane < 4) {
            #pragma unroll
            for (int nt = 0; nt < 4; nt++)
                #pragma unroll
                for (int e = 0; e < 2; e++)
                    colred[wn * 32 + nt * 8 + lane * 2 + e][wm] =
                        colacc[nt * 2 + e];
        }
    }
    __syncthreads();

    if (t < 128) {
        g_rowpart[b][ti][tj][t] = red[t][0] + red[t][1] + red[t][2] + red[t][3];
        if (!diag)
            g_rowpart[b][tj][ti][t] = colred[t][0] + colred[t][1];
    }
}

// One block per batch; the last block to finish also does the final reduction.
__global__ void lse_kernel(float* __restrict__ out) {
    int b = blockIdx.x;
    int t = threadIdx.x;           // 0..511
    int tr = t >> 7, r = t & 127;
    float s = g_rowpart[b][tr][0][r] + g_rowpart[b][tr][1][r]
            + g_rowpart[b][tr][2][r] + g_rowpart[b][tr][3][r];
    float l = logf(s);

    __shared__ float wsum[16];
    #pragma unroll
    for (int o = 16; o > 0; o >>= 1)
        l += __shfl_down_sync(0xffffffffu, l, o);
    if ((t & 31) == 0) wsum[t >> 5] = l;
    __syncthreads();
    __shared__ bool last;
    if (t == 0) {
        float acc = 0.f;
        #pragma unroll
        for (int q = 0; q < 16; q++) acc += wsum[q];
        g_neg_part[b] = acc;
        __threadfence();
        unsigned o = atomicAdd(&g_ctr, 1u);
        last = (o == TWO_B - 1);
    }
    __syncthreads();
    if (!last) return;

    // final reduction (512 threads)
    __threadfence();
    double dp = 0.0, dn = 0.0;
    #pragma unroll
    for (int q = 0; q < 8; q++) dp += (double)g_pos_part[t + q * 512];
    if (t < TWO_B) dn = (double)g_neg_part[t];

    __shared__ double wp[16], wng[16];
    #pragma unroll
    for (int o = 16; o > 0; o >>= 1) {
        dp += __shfl_down_sync(0xffffffffu, dp, o);
        dn += __shfl_down_sync(0xffffffffu, dn, o);
    }
    if ((t & 31) == 0) { wp[t >> 5] = dp; wng[t >> 5] = dn; }
    __syncthreads();
    if (t == 0) {
        double sp = 0.0, sn = 0.0;
        #pragma unroll
        for (int q = 0; q < 16; q++) { sp += wp[q]; sn += wng[q]; }
        double loss_neg = sn / (double)(TWO_B * MSZ);
        double loss_pos = (sp / (double)NROWS) * 2.0;
        out[0] = (float)(loss_neg - loss_pos);
    }
}

extern "C" void kernel_launch(void* const* d_in, const int* in_sizes, int n_in,
                              void* d_out, int out_size) {
    const float* x  = (const float*)d_in[0];
    const float* xp = (const float*)d_in[1];
    float* out = (float*)d_out;

    cudaFuncSetAttribute(gram_kernel,
                         cudaFuncAttributeMaxDynamicSharedMemorySize, 65536);

    normalize_kernel<<<NROWS / 8, 256>>>(x, xp);
    dim3 grid(10, TWO_B);   // 10 tile pairs x 128 batches
    gram_kernel<<<grid, 256, 65536>>>();
    lse_kernel<<<TWO_B, 512>>>(out);
}

// round 6
// speedup vs baseline: 8.5156x; 1.0642x over previous
#include <cuda_runtime.h>
#include <cuda_bf16.h>
#include <cuda_fp8.h>
#include <math.h>
#include <stdint.h>

#define TWO_B 128
#define KCH   256
#define MSZ   512
#define DIM   256
#define NROWS (TWO_B * KCH)   // 32768
#define EPSN  1e-8f

// fp8 normalized rows, batch-major [b][i][d], scaled by 16/sqrt(2): 16 MB
__device__ uint8_t g_z8[(size_t)TWO_B * MSZ * DIM];
// per-row exp-sum partials: [b][row_tile][slot][row_in_tile], each written once
__device__ float g_rowpart[TWO_B][4][4][128];
__device__ float g_pos_part[NROWS / 8];
__device__ float g_neg_part[TWO_B];
__device__ unsigned g_ctr;

__constant__ int TI_LUT[10] = {0,0,0,0,1,1,1,2,2,3};
__constant__ int TJ_LUT[10] = {0,1,2,3,1,2,3,2,3,3};

// ---------------- helpers ----------------
__device__ __forceinline__ uint32_t smem_u32(const void* p) {
    uint32_t a;
    asm("{ .reg .u64 t; cvta.to.shared.u64 t, %1; cvt.u32.u64 %0, t; }"
        : "=r"(a) : "l"(p));
    return a;
}

#define CP_ASYNC16(sdst, gsrc) \
    asm volatile("cp.async.cg.shared.global [%0], [%1], 16;" \
                 :: "r"(sdst), "l"(gsrc) : "memory")
#define CP_COMMIT() asm volatile("cp.async.commit_group;" ::: "memory")
#define CP_WAIT0()  asm volatile("cp.async.wait_group 0;" ::: "memory")

#define LDMATRIX_X4(r, addr) \
    asm volatile("ldmatrix.sync.aligned.m8n8.x4.shared.b16 {%0,%1,%2,%3}, [%4];" \
                 : "=r"((r)[0]), "=r"((r)[1]), "=r"((r)[2]), "=r"((r)[3]) \
                 : "r"(addr))

#define MMA_FP8(c, a, b0, b1) \
    asm volatile("mma.sync.aligned.m16n8k32.row.col.f32.e4m3.e4m3.f32 " \
                 "{%0,%1,%2,%3},{%4,%5,%6,%7},{%8,%9},{%0,%1,%2,%3};" \
                 : "+f"((c)[0]), "+f"((c)[1]), "+f"((c)[2]), "+f"((c)[3]) \
                 : "r"((a)[0]), "r"((a)[1]), "r"((a)[2]), "r"((a)[3]), \
                   "r"(b0), "r"(b1))

// Tile: 128 rows x 256 fp8 (256B/row); cb = 16B column 0..15, XOR-swizzled
__device__ __forceinline__ uint32_t swz8(uint32_t r, uint32_t cb) {
    return r * 256u + ((cb ^ (r & 7u)) << 4);
}

__device__ __forceinline__ uint32_t pack_fp8x4(float a, float b, float c, float d) {
    __nv_fp8x2_storage_t lo = __nv_cvt_float2_to_fp8x2(make_float2(a, b),
                                                       __NV_SATFINITE, __NV_E4M3);
    __nv_fp8x2_storage_t hi = __nv_cvt_float2_to_fp8x2(make_float2(c, d),
                                                       __NV_SATFINITE, __NV_E4M3);
    return (uint32_t)lo | ((uint32_t)hi << 16);
}

// exp(c/64) = 2^(c * 1/(64 ln2)) via MUFU ex2 (rel err ~2^-22)
__device__ __forceinline__ float exp_mufu(float c) {
    const float K2 = 0.022556390446879415f;   // 1/(64*ln2)
    float y;
    asm("ex2.approx.ftz.f32 %0, %1;" : "=f"(y) : "f"(c * K2));
    return y;
}

// ---------------- kernels ----------------
// One warp per row: norms + cosine; write scaled normalized fp8 rows batch-major.
__global__ void normalize_kernel(const float* __restrict__ x,
                                 const float* __restrict__ xp) {
    if (blockIdx.x == 0 && threadIdx.x == 0) g_ctr = 0;

    int wib  = threadIdx.x >> 5;
    int lane = threadIdx.x & 31;
    int row  = blockIdx.x * 8 + wib;

    const float4* xr = (const float4*)(x  + (size_t)row * DIM);
    const float4* pr = (const float4*)(xp + (size_t)row * DIM);
    float4 xa = xr[lane], xb = xr[lane + 32];
    float4 pa = pr[lane], pb = pr[lane + 32];

    float ssx = xa.x*xa.x + xa.y*xa.y + xa.z*xa.z + xa.w*xa.w
              + xb.x*xb.x + xb.y*xb.y + xb.z*xb.z + xb.w*xb.w;
    float ssp = pa.x*pa.x + pa.y*pa.y + pa.z*pa.z + pa.w*pa.w
              + pb.x*pb.x + pb.y*pb.y + pb.z*pb.z + pb.w*pb.w;
    float dt  = xa.x*pa.x + xa.y*pa.y + xa.z*pa.z + xa.w*pa.w
              + xb.x*pb.x + xb.y*pb.y + xb.z*pb.z + xb.w*pb.w;

    #pragma unroll
    for (int o = 16; o > 0; o >>= 1) {
        ssx += __shfl_down_sync(0xffffffffu, ssx, o);
        ssp += __shfl_down_sync(0xffffffffu, ssp, o);
        dt  += __shfl_down_sync(0xffffffffu, dt,  o);
    }
    ssx = __shfl_sync(0xffffffffu, ssx, 0);
    ssp = __shfl_sync(0xffffffffu, ssp, 0);
    dt  = __shfl_sync(0xffffffffu, dt,  0);

    float nx = fmaxf(sqrtf(ssx), EPSN);
    float np = fmaxf(sqrtf(ssp), EPSN);
    float cosv = dt / (nx * np);

    // scale = 16/sqrt(2): dot of stored vectors = 256 * (cos/2) -> c, sim/TEMP = c/64
    const float SCL = 11.313708498984761f;
    float sx = SCL / nx;
    float sp = SCL / np;
    int b = row & (TWO_B - 1);
    int i = row >> 7;

    uint8_t* zx = g_z8 + ((size_t)b * MSZ + i)       * DIM;
    uint8_t* zp = g_z8 + ((size_t)b * MSZ + i + KCH) * DIM;
    *(uint32_t*)(zx + 4 * lane)       = pack_fp8x4(xa.x*sx, xa.y*sx, xa.z*sx, xa.w*sx);
    *(uint32_t*)(zx + 128 + 4 * lane) = pack_fp8x4(xb.x*sx, xb.y*sx, xb.z*sx, xb.w*sx);
    *(uint32_t*)(zp + 4 * lane)       = pack_fp8x4(pa.x*sp, pa.y*sp, pa.z*sp, pa.w*sp);
    *(uint32_t*)(zp + 128 + 4 * lane) = pack_fp8x4(pb.x*sp, pb.y*sp, pb.z*sp, pb.w*sp);

    __shared__ float psum[8];
    if (lane == 0) psum[wib] = cosv;
    __syncthreads();
    if (threadIdx.x == 0) {
        float s = 0.f;
        #pragma unroll
        for (int q = 0; q < 8; q++) s += psum[q];
        g_pos_part[blockIdx.x] = s;
    }
}

// One CTA = one (b, ti<=tj) tile pair. S = A_i @ A_j^T (fp8), MUFU exp, row+col sums.
__global__ __launch_bounds__(256, 2) void gram_kernel() {
    __shared__ float red[128][4];
    __shared__ float colred[128][2];
    extern __shared__ char dyn[];

    int t    = threadIdx.x;
    int wid  = t >> 5;
    int lane = t & 31;
    int b    = blockIdx.y;
    int p    = blockIdx.x;
    int ti   = TI_LUT[p];
    int tj   = TJ_LUT[p];
    bool diag = (ti == tj);

    int wm = wid >> 2;          // 0..1 : warp m-offset = wm*64
    int wn = wid & 3;           // 0..3 : warp n-offset = wn*32

    uint32_t sA = smem_u32(dyn);
    uint32_t sBj = diag ? sA : (sA + 32768);

    const uint8_t* Z = g_z8 + (size_t)b * MSZ * DIM;
    {   // load tiles: 2048 16B chunks each (32KB)
        const char* gA = (const char*)(Z + (size_t)ti * 128 * DIM);
        const char* gB = (const char*)(Z + (size_t)tj * 128 * DIM);
        #pragma unroll
        for (int q = 0; q < 8; q++) {
            int f = t + q * 256;
            uint32_t off = swz8(f >> 4, f & 15);
            CP_ASYNC16(sA + off, gA + (size_t)f * 16);
            if (!diag) CP_ASYNC16(sBj + off, gB + (size_t)f * 16);
        }
        CP_COMMIT();
        CP_WAIT0();
        __syncthreads();
    }

    float C[4][4][4];
    #pragma unroll
    for (int mt = 0; mt < 4; mt++)
        #pragma unroll
        for (int nt = 0; nt < 4; nt++)
            #pragma unroll
            for (int e = 0; e < 4; e++) C[mt][nt][e] = 0.f;

    #pragma unroll
    for (int k = 0; k < 8; k++) {           // 8 steps of k=32 fp8
        uint32_t cb = 2u * k + (lane >> 4);
        uint32_t afr[4][4], bfr[2][4];
        #pragma unroll
        for (int mt = 0; mt < 4; mt++) {
            uint32_t r = wm * 64 + mt * 16 + (lane & 15);
            LDMATRIX_X4(afr[mt], sA + swz8(r, cb));
        }
        #pragma unroll
        for (int h = 0; h < 2; h++) {
            uint32_t r = wn * 32 + h * 16 + (lane & 15);
            LDMATRIX_X4(bfr[h], sBj + swz8(r, cb));
        }
        #pragma unroll
        for (int mt = 0; mt < 4; mt++)
            #pragma unroll
            for (int nt = 0; nt < 4; nt++) {
                uint32_t b0 = bfr[nt >> 1][(nt & 1) ? 1 : 0];
                uint32_t b1 = bfr[nt >> 1][(nt & 1) ? 3 : 2];
                MMA_FP8(C[mt][nt], afr[mt], b0, b1);
            }
    }

    // epilogue: e = exp(c/64) via MUFU; diag mask only in diagonal tiles
    float rowacc[8], colacc[8];
    #pragma unroll
    for (int q = 0; q < 8; q++) { rowacc[q] = 0.f; colacc[q] = 0.f; }

    if (diag) {
        #pragma unroll
        for (int mt = 0; mt < 4; mt++) {
            #pragma unroll
            for (int h = 0; h < 2; h++) {
                int li = wm * 64 + mt * 16 + (lane >> 2) + 8 * h;
                #pragma unroll
                for (int nt = 0; nt < 4; nt++) {
                    #pragma unroll
                    for (int e = 0; e < 2; e++) {
                        float ex = exp_mufu(C[mt][nt][h * 2 + e]);
                        int lj = wn * 32 + nt * 8 + (lane & 3) * 2 + e;
                        ex = (li == lj) ? 0.f : ex;
                        rowacc[mt * 2 + h] += ex;
                        colacc[nt * 2 + e] += ex;
                    }
                }
            }
        }
    } else {
        #pragma unroll
        for (int mt = 0; mt < 4; mt++) {
            #pragma unroll
            for (int h = 0; h < 2; h++) {
                #pragma unroll
                for (int nt = 0; nt < 4; nt++) {
                    #pragma unroll
                    for (int e = 0; e < 2; e++) {
                        float ex = exp_mufu(C[mt][nt][h * 2 + e]);
                        rowacc[mt * 2 + h] += ex;
                        colacc[nt * 2 + e] += ex;
                    }
                }
            }
        }
    }

    // row reduction: over lane&3, then over wn via smem
    #pragma unroll
    for (int q = 0; q < 8; q++) {
        rowacc[q] += __shfl_xor_sync(0xffffffffu, rowacc[q], 1);
        rowacc[q] += __shfl_xor_sync(0xffffffffu, rowacc[q], 2);
    }
    if ((lane & 3) == 0) {
        #pragma unroll
        for (int mt = 0; mt < 4; mt++)
            #pragma unroll
            for (int h = 0; h < 2; h++)
                red[wm * 64 + mt * 16 + (lane >> 2) + 8 * h][wn] =
                    rowacc[mt * 2 + h];
    }

    // col reduction (off-diag only): over lane>>2, then over wm
    if (!diag) {
        #pragma unroll
        for (int q = 0; q < 8; q++) {
            colacc[q] += __shfl_xor_sync(0xffffffffu, colacc[q], 4);
            colacc[q] += __shfl_xor_sync(0xffffffffu, colacc[q], 8);
            colacc[q] += __shfl_xor_sync(0xffffffffu, colacc[q], 16);
        }
        if (lane < 4) {
            #pragma unroll
            for (int nt = 0; nt < 4; nt++)
                #pragma unroll
                for (int e = 0; e < 2; e++)
                    colred[wn * 32 + nt * 8 + lane * 2 + e][wm] =
                        colacc[nt * 2 + e];
        }
    }
    __syncthreads();

    if (t < 128) {
        g_rowpart[b][ti][tj][t] = red[t][0] + red[t][1] + red[t][2] + red[t][3];
        if (!diag)
            g_rowpart[b][tj][ti][t] = colred[t][0] + colred[t][1];
    }
}

// One block per batch; the last block to finish also does the final reduction.
__global__ void lse_kernel(float* __restrict__ out) {
    int b = blockIdx.x;
    int t = threadIdx.x;           // 0..511
    int tr = t >> 7, r = t & 127;
    float s = g_rowpart[b][tr][0][r] + g_rowpart[b][tr][1][r]
            + g_rowpart[b][tr][2][r] + g_rowpart[b][tr][3][r];
    float l = logf(s);

    __shared__ float wsum[16];
    #pragma unroll
    for (int o = 16; o > 0; o >>= 1)
        l += __shfl_down_sync(0xffffffffu, l, o);
    if ((t & 31) == 0) wsum[t >> 5] = l;
    __syncthreads();
    __shared__ bool last;
    if (t == 0) {
        float acc = 0.f;
        #pragma unroll
        for (int q = 0; q < 16; q++) acc += wsum[q];
        g_neg_part[b] = acc;
        __threadfence();
        unsigned o = atomicAdd(&g_ctr, 1u);
        last = (o == TWO_B - 1);
    }
    __syncthreads();
    if (!last) return;

    // final reduction (512 threads)
    __threadfence();
    double dp = 0.0, dn = 0.0;
    #pragma unroll
    for (int q = 0; q < 8; q++) dp += (double)g_pos_part[t + q * 512];
    if (t < TWO_B) dn = (double)g_neg_part[t];

    __shared__ double wp[16], wng[16];
    #pragma unroll
    for (int o = 16; o > 0; o >>= 1) {
        dp += __shfl_down_sync(0xffffffffu, dp, o);
        dn += __shfl_down_sync(0xffffffffu, dn, o);
    }
    if ((t & 31) == 0) { wp[t >> 5] = dp; wng[t >> 5] = dn; }
    __syncthreads();
    if (t == 0) {
        double sp = 0.0, sn = 0.0;
        #pragma unroll
        for (int q = 0; q < 16; q++) { sp += wp[q]; sn += wng[q]; }
        double loss_neg = sn / (double)(TWO_B * MSZ);
        double loss_pos = (sp / (double)NROWS) * 2.0;
        out[0] = (float)(loss_neg - loss_pos);
    }
}

extern "C" void kernel_launch(void* const* d_in, const int* in_sizes, int n_in,
                              void* d_out, int out_size) {
    const float* x  = (const float*)d_in[0];
    const float* xp = (const float*)d_in[1];
    float* out = (float*)d_out;

    cudaFuncSetAttribute(gram_kernel,
                         cudaFuncAttributeMaxDynamicSharedMemorySize, 65536);

    normalize_kernel<<<NROWS / 8, 256>>>(x, xp);
    dim3 grid(10, TWO_B);   // 10 tile pairs x 128 batches
    gram_kernel<<<grid, 256, 65536>>>();
    lse_kernel<<<TWO_B, 512>>>(out);
}